// round 8
// baseline (speedup 1.0000x reference)
#include <cuda_runtime.h>
#include <cuda_fp16.h>
#include <cstdint>

#define D    128
#define DE   32
#define NET  5
#define MAXN 50000
#define CAP_TOTAL 4000000
#define KW   (D + DE)       // 160

// ---- scratch (device globals: allocation-free; bss zero-init at load) ----
__device__ __half g_xh [(size_t)MAXN * D];            // fp16 op_feats
__device__ __half g_S1h[(size_t)NET * MAXN * D];      // fp16 per-etype mean of src feats
__device__ __half g_S2h[(size_t)NET * MAXN * DE];     // fp16 per-etype mean of edge feats
__device__ __half g_Wh [(size_t)NET * D * KW];        // fp16 weights, TRANSPOSED [et][n][k]
__device__ __half g_efh[(size_t)CAP_TOTAL * DE];      // fp16 ef rows, CSR order
__device__ float  g_mask[(size_t)NET * MAXN];
__device__ int    g_deg[(size_t)NET * MAXN];          // zeroed by gemm epilogue
__device__ int    g_off[(size_t)NET * MAXN];
__device__ int    g_cur[(size_t)NET * MAXN];
__device__ int    g_csr[(size_t)CAP_TOTAL];           // src only
__device__ int    g_total;                            // zeroed by gemm epilogue

struct EdgeMeta {
    const int*   src[NET];
    const int*   dst[NET];
    const float* ef[NET];
    int          E[NET];
};
struct WPtrs { const float* W[NET]; };

// ---------------------------------------------------------------------------
// 1) fused: x->fp16 | W->fp16^T | edge count
// ---------------------------------------------------------------------------
__global__ void count_prep_kernel(const float* __restrict__ x, WPtrs wp,
                                  EdgeMeta em, int n, int nx, int nw)
{
    int i = blockIdx.x * blockDim.x + threadIdx.x;

    if (i < nx) {
        float4 v0 = __ldg(reinterpret_cast<const float4*>(x) + 2 * i);
        float4 v1 = __ldg(reinterpret_cast<const float4*>(x) + 2 * i + 1);
        __half2 h[4];
        h[0] = __floats2half2_rn(v0.x, v0.y);
        h[1] = __floats2half2_rn(v0.z, v0.w);
        h[2] = __floats2half2_rn(v1.x, v1.y);
        h[3] = __floats2half2_rn(v1.z, v1.w);
        reinterpret_cast<uint4*>(g_xh)[i] = *reinterpret_cast<uint4*>(h);
        return;
    }
    i -= nx;
    if (i < nw) {
        int et = i / (D * KW);
        int r  = i % (D * KW);
        int nn = r / KW;
        int k  = r % KW;
        const float* W = (et == 0) ? wp.W[0] : (et == 1) ? wp.W[1]
                       : (et == 2) ? wp.W[2] : (et == 3) ? wp.W[3] : wp.W[4];
        g_Wh[i] = __float2half_rn(__ldg(&W[k * D + nn]));
        return;
    }
    i -= nw;
    const int* dstp;
    int base;
    if (i < em.E[0]) { dstp = em.dst[0]; base = 0; }
    else {
        i -= em.E[0];
        if (i < em.E[1]) { dstp = em.dst[1]; base = n; }
        else {
            i -= em.E[1];
            if (i < em.E[2]) { dstp = em.dst[2]; base = 2 * n; }
            else {
                i -= em.E[2];
                if (i < em.E[3]) { dstp = em.dst[3]; base = 3 * n; }
                else {
                    i -= em.E[3];
                    if (i >= em.E[4]) return;
                    dstp = em.dst[4]; base = 4 * n;
                }
            }
        }
    }
    atomicAdd(&g_deg[base + __ldg(&dstp[i])], 1);
}

// ---------------------------------------------------------------------------
// 2) alloc: segment offsets via block scan + one global atomic
// ---------------------------------------------------------------------------
__global__ void alloc_kernel(int nelem)
{
    __shared__ int wsum[8];
    int tid  = threadIdx.x;
    int i    = blockIdx.x * 256 + tid;
    int lane = tid & 31;
    int w    = tid >> 5;

    int d = (i < nelem) ? g_deg[i] : 0;
    int v = d;
#pragma unroll
    for (int o = 1; o < 32; o <<= 1) {
        int t = __shfl_up_sync(0xffffffffu, v, o);
        if (lane >= o) v += t;
    }
    if (lane == 31) wsum[w] = v;
    __syncthreads();
    if (tid == 0) {
        int s = 0;
#pragma unroll
        for (int j = 0; j < 8; j++) { int t = wsum[j]; wsum[j] = s; s += t; }
        int b = atomicAdd(&g_total, s);
#pragma unroll
        for (int j = 0; j < 8; j++) wsum[j] += b;
    }
    __syncthreads();
    int off = wsum[w] + v - d;
    if (i < nelem) { g_off[i] = off; g_cur[i] = off; }
}

// ---------------------------------------------------------------------------
// 3) fill: CSR src + ef row converted fp16, scattered into CSR order
// ---------------------------------------------------------------------------
__global__ void fill_kernel(EdgeMeta em, int n)
{
    int et = blockIdx.y;
    int i  = blockIdx.x * blockDim.x + threadIdx.x;
    const int* dst = (et == 0) ? em.dst[0] : (et == 1) ? em.dst[1] : (et == 2) ? em.dst[2]
                   : (et == 3) ? em.dst[3] : em.dst[4];
    const int* src = (et == 0) ? em.src[0] : (et == 1) ? em.src[1] : (et == 2) ? em.src[2]
                   : (et == 3) ? em.src[3] : em.src[4];
    const float* efp = (et == 0) ? em.ef[0] : (et == 1) ? em.ef[1] : (et == 2) ? em.ef[2]
                     : (et == 3) ? em.ef[3] : em.ef[4];
    if (i < em.E[et]) {
        int d = __ldg(&dst[i]);
        int s = __ldg(&src[i]);
        int pos = atomicAdd(&g_cur[et * n + d], 1);
        g_csr[pos] = s;

        // convert this edge's ef row to fp16 and store at CSR slot (coalesced
        // read, scattered fire-and-forget 64B store)
        const float4* ep = reinterpret_cast<const float4*>(efp + (size_t)i * DE);
        uint4* op = reinterpret_cast<uint4*>(g_efh + (size_t)pos * DE);
#pragma unroll
        for (int c = 0; c < 4; c++) {
            float4 v0 = __ldg(ep + 2 * c);
            float4 v1 = __ldg(ep + 2 * c + 1);
            __half2 h[4];
            h[0] = __floats2half2_rn(v0.x, v0.y);
            h[1] = __floats2half2_rn(v0.z, v0.w);
            h[2] = __floats2half2_rn(v1.x, v1.y);
            h[3] = __floats2half2_rn(v1.z, v1.w);
            op[c] = *reinterpret_cast<uint4*>(h);
        }
    }
}

// ---------------------------------------------------------------------------
// 4) gather: x-only (R6 best form). One warp per (etype,node); 2 edges/iter,
//    16 lanes/edge; 8 fp32 accumulators.
// ---------------------------------------------------------------------------
__global__ void __launch_bounds__(256, 6)
gather_kernel(int n)
{
    int gw   = (blockIdx.x * blockDim.x + threadIdx.x) >> 5;
    int lane = threadIdx.x & 31;
    if (gw >= NET * n) return;

    int beg = g_off[gw];
    int cnt = g_deg[gw];
    int end = beg + cnt;

    int half = lane >> 4;
    int ql   = lane & 15;

    float a[8];
#pragma unroll
    for (int k = 0; k < 8; k++) a[k] = 0.f;

    for (int base = beg; base < end; base += 32) {
        int take = min(32, end - base);
        int mm = 0;
        if (lane < take) mm = __ldg(&g_csr[base + lane]);
#pragma unroll
        for (int j = 0; j < 16; j++) {
            if (2 * j >= take) break;
            int e    = 2 * j + half;
            int sidx = __shfl_sync(0xffffffffu, mm, e);
            if (e < take) {
                uint4 hv = __ldg(reinterpret_cast<const uint4*>(
                               g_xh + (size_t)sidx * D) + ql);
                __half2* hp = reinterpret_cast<__half2*>(&hv);
#pragma unroll
                for (int c = 0; c < 4; c++) {
                    float2 f = __half22float2(hp[c]);
                    a[2 * c]     += f.x;
                    a[2 * c + 1] += f.y;
                }
            }
        }
    }

#pragma unroll
    for (int k = 0; k < 8; k++) a[k] += __shfl_xor_sync(0xffffffffu, a[k], 16);

    float inv = (cnt > 0) ? (1.0f / (float)cnt) : 0.0f;

    if (half == 0) {
        __half2 o[4];
#pragma unroll
        for (int k = 0; k < 4; k++)
            o[k] = __floats2half2_rn(a[2 * k] * inv, a[2 * k + 1] * inv);
        reinterpret_cast<uint4*>(g_S1h + (size_t)gw * D)[ql] =
            *reinterpret_cast<uint4*>(o);
        if (ql == 0) g_mask[gw] = (cnt > 0) ? 1.0f : 0.0f;
    }
}

// ---------------------------------------------------------------------------
// 4b) ef mean: one warp per (etype,node); CONTIGUOUS fp16 rows in CSR order.
//     8 rows per iteration (4 lanes/row), pure streaming.
// ---------------------------------------------------------------------------
__global__ void __launch_bounds__(256, 6)
efmean_kernel(int n)
{
    int gw   = (blockIdx.x * blockDim.x + threadIdx.x) >> 5;
    int lane = threadIdx.x & 31;
    if (gw >= NET * n) return;

    int beg = g_off[gw];
    int cnt = g_deg[gw];

    int r  = lane >> 2;   // row-in-group 0..7
    int ql = lane & 3;    // uint4 index within 64B row

    float a[8];
#pragma unroll
    for (int k = 0; k < 8; k++) a[k] = 0.f;

    for (int j = 0; j < cnt; j += 8) {
        int e = j + r;
        if (e < cnt) {
            uint4 hv = __ldg(reinterpret_cast<const uint4*>(
                           g_efh + (size_t)(beg + e) * DE) + ql);
            __half2* hp = reinterpret_cast<__half2*>(&hv);
#pragma unroll
            for (int c = 0; c < 4; c++) {
                float2 f = __half22float2(hp[c]);
                a[2 * c]     += f.x;
                a[2 * c + 1] += f.y;
            }
        }
    }
    // reduce across the 8 row-groups (lanes with equal ql)
#pragma unroll
    for (int k = 0; k < 8; k++) {
        a[k] += __shfl_xor_sync(0xffffffffu, a[k], 4);
        a[k] += __shfl_xor_sync(0xffffffffu, a[k], 8);
        a[k] += __shfl_xor_sync(0xffffffffu, a[k], 16);
    }

    if (lane < 4) {
        float inv = (cnt > 0) ? (1.0f / (float)cnt) : 0.0f;
        __half2 o[4];
#pragma unroll
        for (int k = 0; k < 4; k++)
            o[k] = __floats2half2_rn(a[2 * k] * inv, a[2 * k + 1] * inv);
        reinterpret_cast<uint4*>(g_S2h + (size_t)gw * DE)[lane] =
            *reinterpret_cast<uint4*>(o);
    }
}

// ---------------------------------------------------------------------------
// 5) fused GEMM (fp16 HMMA, fp32 accum) + epilogue + state reset
// ---------------------------------------------------------------------------
#define BM  128
#define SAH 168

__device__ __forceinline__ void mma_f16(float* c, const unsigned* a, const unsigned* b)
{
    asm volatile(
        "mma.sync.aligned.m16n8k16.row.col.f32.f16.f16.f32 "
        "{%0,%1,%2,%3}, {%4,%5,%6,%7}, {%8,%9}, {%0,%1,%2,%3};"
        : "+f"(c[0]), "+f"(c[1]), "+f"(c[2]), "+f"(c[3])
        : "r"(a[0]), "r"(a[1]), "r"(a[2]), "r"(a[3]),
          "r"(b[0]), "r"(b[1]));
}

__global__ void __launch_bounds__(256, 2)
gemm_epi_kernel(const float* __restrict__ x,
                const float* __restrict__ b0, const float* __restrict__ b1,
                const float* __restrict__ b2, const float* __restrict__ b3,
                const float* __restrict__ b4,
                float* __restrict__ out, int n)
{
    extern __shared__ __half sm[];
    __half* As = sm;                    // [BM][SAH]
    __half* Bs = sm + (size_t)BM * SAH; // [D][SAH]

    __shared__ float msk[NET][BM];
    __shared__ float bsm[NET][D];

    const float* bp[NET] = {b0, b1, b2, b3, b4};

    int tid  = threadIdx.x;
    int lane = tid & 31;
    int warp = tid >> 5;
    int wm   = (warp & 1) * 64;
    int wn   = (warp >> 1) * 32;
    int lrow = lane >> 2;
    int lcol = lane & 3;
    int row0 = blockIdx.x * BM;

#pragma unroll
    for (int et = 0; et < NET; et++) {
        if (tid < BM) {
            int row = row0 + tid;
            msk[et][tid] = (row < n) ? g_mask[(size_t)et * n + row] : 0.f;
        }
        if (tid < D) bsm[et][tid] = bp[et][tid];
    }

    float c[4][4][4];
#pragma unroll
    for (int s = 0; s < 4; s++)
#pragma unroll
        for (int t = 0; t < 4; t++)
#pragma unroll
            for (int r = 0; r < 4; r++) c[s][t][r] = 0.f;

    __syncthreads();

#pragma unroll 1
    for (int et = 0; et < NET; et++) {
        const __half* __restrict__ S1e = g_S1h + (size_t)et * n * D;
        const __half* __restrict__ S2e = g_S2h + (size_t)et * n * DE;
        const __half* __restrict__ Whe = g_Wh  + (size_t)et * D * KW;

#pragma unroll
        for (int t = 0; t < 10; t++) {
            int idx = tid + t * 256;
            int row = idx / 20;
            int cc  = idx % 20;
            int grow = row0 + row;
            uint4 v = make_uint4(0u, 0u, 0u, 0u);
            if (grow < n) {
                v = (cc < 16)
                  ? __ldg(reinterpret_cast<const uint4*>(S1e + (size_t)grow * D)  + cc)
                  : __ldg(reinterpret_cast<const uint4*>(S2e + (size_t)grow * DE) + (cc - 16));
            }
            *reinterpret_cast<uint4*>(As + (size_t)row * SAH + cc * 8) = v;
        }
#pragma unroll
        for (int t = 0; t < 10; t++) {
            int idx = tid + t * 256;
            int row = idx / 20;
            int cc  = idx % 20;
            uint4 v = __ldg(reinterpret_cast<const uint4*>(Whe + (size_t)row * KW) + cc);
            *reinterpret_cast<uint4*>(Bs + (size_t)row * SAH + cc * 8) = v;
        }
        __syncthreads();

#pragma unroll
        for (int kk = 0; kk < 10; kk++) {
            int k0 = kk * 16;
            unsigned a[4][4], b[4][2];
#pragma unroll
            for (int s = 0; s < 4; s++) {
                int m = wm + s * 16 + lrow;
                const __half* p0 = As + (size_t)m * SAH + k0 + 2 * lcol;
                a[s][0] = *reinterpret_cast<const unsigned*>(p0);
                a[s][1] = *reinterpret_cast<const unsigned*>(p0 + 8 * SAH);
                a[s][2] = *reinterpret_cast<const unsigned*>(p0 + 8);
                a[s][3] = *reinterpret_cast<const unsigned*>(p0 + 8 * SAH + 8);
            }
#pragma unroll
            for (int t = 0; t < 4; t++) {
                int nn = wn + t * 8 + lrow;
                const __half* p0 = Bs + (size_t)nn * SAH + k0 + 2 * lcol;
                b[t][0] = *reinterpret_cast<const unsigned*>(p0);
                b[t][1] = *reinterpret_cast<const unsigned*>(p0 + 8);
            }
#pragma unroll
            for (int s = 0; s < 4; s++)
#pragma unroll
                for (int t = 0; t < 4; t++)
                    mma_f16(c[s][t], a[s], b[t]);
        }
        __syncthreads();
    }

    // epilogue
#pragma unroll
    for (int s = 0; s < 4; s++) {
#pragma unroll
        for (int h = 0; h < 2; h++) {
            int mloc = wm + s * 16 + lrow + h * 8;
            int grow = row0 + mloc;
            if (grow >= n) continue;
            float mk[NET];
#pragma unroll
            for (int et = 0; et < NET; et++) mk[et] = msk[et][mloc];
#pragma unroll
            for (int t = 0; t < 4; t++) {
                int ncol = wn + t * 8 + lcol * 2;
                float bs0 = 0.f, bs1 = 0.f;
#pragma unroll
                for (int et = 0; et < NET; et++) {
                    if (mk[et] > 0.f) {
                        bs0 += bsm[et][ncol];
                        bs1 += bsm[et][ncol + 1];
                    }
                }
                float c0 = c[s][t][h * 2 + 0];
                float c1 = c[s][t][h * 2 + 1];
                const float* xp = x + (size_t)grow * D + ncol;
                float2 o;
                o.x = fmaxf(xp[0] + (c0 + bs0) * 0.2f, 0.f);
                o.y = fmaxf(xp[1] + (c1 + bs1) * 0.2f, 0.f);
                *reinterpret_cast<float2*>(out + (size_t)grow * D + ncol) = o;
            }
        }
    }

    // state reset for next replay: zero degrees + allocator
    int zi = blockIdx.x * blockDim.x + threadIdx.x;
    int zs = gridDim.x * blockDim.x;
    for (int z = zi; z < NET * n; z += zs) g_deg[z] = 0;
    if (zi == 0) g_total = 0;
}

// ---------------------------------------------------------------------------
extern "C" void kernel_launch(void* const* d_in, const int* in_sizes, int n_in,
                              void* d_out, int out_size)
{
    const float* x = (const float*)d_in[0];
    int n = in_sizes[0] / D;
    if (n > MAXN) return;

    EdgeMeta em;
    WPtrs wp;
    const float* b[NET];
    int maxE = 0, totE = 0;
    for (int et = 0; et < NET; et++) {
        em.ef[et]  = (const float*)d_in[1 + 5 * et + 0];
        wp.W[et]   = (const float*)d_in[1 + 5 * et + 1];
        b[et]      = (const float*)d_in[1 + 5 * et + 2];
        em.src[et] = (const int*)  d_in[1 + 5 * et + 3];
        em.dst[et] = (const int*)  d_in[1 + 5 * et + 4];
        em.E[et]   = in_sizes[1 + 5 * et + 3];
        if (em.E[et] > maxE) maxE = em.E[et];
        totE += em.E[et];
    }
    if (totE > CAP_TOTAL) return;
    float* out = (float*)d_out;

    int nelem = NET * n;

    static int smem_bytes = 2 * BM * SAH * (int)sizeof(__half);
    cudaFuncSetAttribute(gemm_epi_kernel,
                         cudaFuncAttributeMaxDynamicSharedMemorySize, smem_bytes);

    // 1) fused prep + count
    {
        int nx = n * D / 8;
        int nw = NET * D * KW;
        int work = nx + nw + totE;
        count_prep_kernel<<<(work + 255) / 256, 256>>>(x, wp, em, n, nx, nw);
    }
    // 2) alloc
    alloc_kernel<<<(nelem + 255) / 256, 256>>>(nelem);
    // 3) fill (CSR + ef reorder to fp16)
    {
        dim3 grid((maxE + 255) / 256, NET);
        fill_kernel<<<grid, 256>>>(em, n);
    }
    // 4) gather x-only (profiled launch)
    {
        int blocks = (nelem * 32 + 255) / 256;
        gather_kernel<<<blocks, 256>>>(n);
    }
    // 4b) ef means (contiguous streaming)
    {
        int blocks = (nelem * 32 + 255) / 256;
        efmean_kernel<<<blocks, 256>>>(n);
    }
    // 5) fused GEMM + epilogue + reset
    {
        int blocks = (n + BM - 1) / BM;
        gemm_epi_kernel<<<blocks, 256, smem_bytes>>>(
            x, b[0], b[1], b[2], b[3], b[4], out, n);
    }
}

// round 9
// speedup vs baseline: 1.1761x; 1.1761x over previous
#include <cuda_runtime.h>
#include <cuda_fp16.h>
#include <cstdint>

#define D    128
#define DE   32
#define NET  5
#define MAXN 50000
#define CAP_TOTAL 4000000
#define KW   (D + DE)       // 160

// ---- scratch (device globals: allocation-free; bss zero-init at load) ----
__device__ __half g_xh [(size_t)MAXN * D];            // fp16 op_feats
__device__ __half g_S1h[(size_t)NET * MAXN * D];      // fp16 per-etype mean of src feats
__device__ __half g_S2h[(size_t)NET * MAXN * DE];     // fp16 per-etype mean of edge feats
__device__ __half g_Wh [(size_t)NET * D * KW];        // fp16 weights, TRANSPOSED [et][n][k]
__device__ float  g_mask[(size_t)NET * MAXN];
__device__ int    g_deg[(size_t)NET * MAXN];          // zeroed by gemm epilogue
__device__ int    g_off[(size_t)NET * MAXN];
__device__ int    g_cur[(size_t)NET * MAXN];
__device__ int2   g_csr[(size_t)CAP_TOTAL];           // (src, edge_id)
__device__ int    g_total;                            // zeroed by gemm epilogue

struct EdgeMeta {
    const int*   src[NET];
    const int*   dst[NET];
    const float* ef[NET];
    int          E[NET];
};
struct WPtrs { const float* W[NET]; };

// ---------------------------------------------------------------------------
// 1) fused: x->fp16 | W->fp16^T | edge count
// ---------------------------------------------------------------------------
__global__ void count_prep_kernel(const float* __restrict__ x, WPtrs wp,
                                  EdgeMeta em, int n, int nx, int nw)
{
    int i = blockIdx.x * blockDim.x + threadIdx.x;

    if (i < nx) {
        float4 v0 = __ldg(reinterpret_cast<const float4*>(x) + 2 * i);
        float4 v1 = __ldg(reinterpret_cast<const float4*>(x) + 2 * i + 1);
        __half2 h[4];
        h[0] = __floats2half2_rn(v0.x, v0.y);
        h[1] = __floats2half2_rn(v0.z, v0.w);
        h[2] = __floats2half2_rn(v1.x, v1.y);
        h[3] = __floats2half2_rn(v1.z, v1.w);
        reinterpret_cast<uint4*>(g_xh)[i] = *reinterpret_cast<uint4*>(h);
        return;
    }
    i -= nx;
    if (i < nw) {
        int et = i / (D * KW);
        int r  = i % (D * KW);
        int nn = r / KW;
        int k  = r % KW;
        const float* W = (et == 0) ? wp.W[0] : (et == 1) ? wp.W[1]
                       : (et == 2) ? wp.W[2] : (et == 3) ? wp.W[3] : wp.W[4];
        g_Wh[i] = __float2half_rn(__ldg(&W[k * D + nn]));
        return;
    }
    i -= nw;
    const int* dstp;
    int base;
    if (i < em.E[0]) { dstp = em.dst[0]; base = 0; }
    else {
        i -= em.E[0];
        if (i < em.E[1]) { dstp = em.dst[1]; base = n; }
        else {
            i -= em.E[1];
            if (i < em.E[2]) { dstp = em.dst[2]; base = 2 * n; }
            else {
                i -= em.E[2];
                if (i < em.E[3]) { dstp = em.dst[3]; base = 3 * n; }
                else {
                    i -= em.E[3];
                    if (i >= em.E[4]) return;
                    dstp = em.dst[4]; base = 4 * n;
                }
            }
        }
    }
    atomicAdd(&g_deg[base + __ldg(&dstp[i])], 1);
}

// ---------------------------------------------------------------------------
// 2) alloc: segment offsets via block scan + one global atomic
// ---------------------------------------------------------------------------
__global__ void alloc_kernel(int nelem)
{
    __shared__ int wsum[8];
    int tid  = threadIdx.x;
    int i    = blockIdx.x * 256 + tid;
    int lane = tid & 31;
    int w    = tid >> 5;

    int d = (i < nelem) ? g_deg[i] : 0;
    int v = d;
#pragma unroll
    for (int o = 1; o < 32; o <<= 1) {
        int t = __shfl_up_sync(0xffffffffu, v, o);
        if (lane >= o) v += t;
    }
    if (lane == 31) wsum[w] = v;
    __syncthreads();
    if (tid == 0) {
        int s = 0;
#pragma unroll
        for (int j = 0; j < 8; j++) { int t = wsum[j]; wsum[j] = s; s += t; }
        int b = atomicAdd(&g_total, s);
#pragma unroll
        for (int j = 0; j < 8; j++) wsum[j] += b;
    }
    __syncthreads();
    int off = wsum[w] + v - d;
    if (i < nelem) { g_off[i] = off; g_cur[i] = off; }
}

// ---------------------------------------------------------------------------
// 3) fill CSR: (src, edge_id), one int2 store per edge
// ---------------------------------------------------------------------------
__global__ void fill_kernel(EdgeMeta em, int n)
{
    int et = blockIdx.y;
    int i  = blockIdx.x * blockDim.x + threadIdx.x;
    const int* dst = (et == 0) ? em.dst[0] : (et == 1) ? em.dst[1] : (et == 2) ? em.dst[2]
                   : (et == 3) ? em.dst[3] : em.dst[4];
    const int* src = (et == 0) ? em.src[0] : (et == 1) ? em.src[1] : (et == 2) ? em.src[2]
                   : (et == 3) ? em.src[3] : em.src[4];
    if (i < em.E[et]) {
        int d = __ldg(&dst[i]);
        int s = __ldg(&src[i]);
        int pos = atomicAdd(&g_cur[et * n + d], 1);
        g_csr[pos] = make_int2(s, i);
    }
}

// ---------------------------------------------------------------------------
// 3b) ef mean: one warp per (etype,node); feature-per-lane — each edge is ONE
//     fully-coalesced 128B load; lane owns feature `lane`; no reduction.
// ---------------------------------------------------------------------------
__global__ void __launch_bounds__(256, 6)
efmean_kernel(EdgeMeta em, int n)
{
    int gw   = (blockIdx.x * blockDim.x + threadIdx.x) >> 5;
    int lane = threadIdx.x & 31;
    if (gw >= NET * n) return;

    int et = gw / n;
    const float* __restrict__ ef =
        (et == 0) ? em.ef[0] : (et == 1) ? em.ef[1] : (et == 2) ? em.ef[2]
                  : (et == 3) ? em.ef[3] : em.ef[4];

    int beg = g_off[gw];
    int cnt = g_deg[gw];
    int end = beg + cnt;

    float acc = 0.f;

    for (int base = beg; base < end; base += 32) {
        int take = min(32, end - base);
        int2 mm = make_int2(0, 0);
        if (lane < take) mm = __ldg(&g_csr[base + lane]);
#pragma unroll
        for (int j = 0; j < 32; j += 4) {
            if (j >= take) break;                 // uniform early exit
            int e0 = __shfl_sync(0xffffffffu, mm.y, j + 0);
            int e1 = __shfl_sync(0xffffffffu, mm.y, j + 1);
            int e2 = __shfl_sync(0xffffffffu, mm.y, j + 2);
            int e3 = __shfl_sync(0xffffffffu, mm.y, j + 3);
            float v0 = 0.f, v1 = 0.f, v2 = 0.f, v3 = 0.f;
            v0 = __ldg(ef + (size_t)e0 * DE + lane);
            if (j + 1 < take) v1 = __ldg(ef + (size_t)e1 * DE + lane);
            if (j + 2 < take) v2 = __ldg(ef + (size_t)e2 * DE + lane);
            if (j + 3 < take) v3 = __ldg(ef + (size_t)e3 * DE + lane);
            acc += (v0 + v1) + (v2 + v3);
        }
    }

    float inv = (cnt > 0) ? (1.0f / (float)cnt) : 0.0f;
    float m  = acc * inv;
    float hi = __shfl_down_sync(0xffffffffu, m, 1);
    if ((lane & 1) == 0) {
        __half2 h = __floats2half2_rn(m, hi);
        reinterpret_cast<__half2*>(g_S2h + (size_t)gw * DE)[lane >> 1] = h;
    }
}

// ---------------------------------------------------------------------------
// 4) gather: x-only (R8 measured form). One warp per (etype,node);
//    2 edges/iter, 16 lanes/edge; 8 fp32 accumulators.
// ---------------------------------------------------------------------------
__global__ void __launch_bounds__(256, 6)
gather_kernel(int n)
{
    int gw   = (blockIdx.x * blockDim.x + threadIdx.x) >> 5;
    int lane = threadIdx.x & 31;
    if (gw >= NET * n) return;

    int beg = g_off[gw];
    int cnt = g_deg[gw];
    int end = beg + cnt;

    int half = lane >> 4;
    int ql   = lane & 15;

    float a[8];
#pragma unroll
    for (int k = 0; k < 8; k++) a[k] = 0.f;

    for (int base = beg; base < end; base += 32) {
        int take = min(32, end - base);
        int mm = 0;
        if (lane < take) mm = __ldg(&g_csr[base + lane]).x;
#pragma unroll
        for (int j = 0; j < 16; j++) {
            if (2 * j >= take) break;
            int e    = 2 * j + half;
            int sidx = __shfl_sync(0xffffffffu, mm, e);
            if (e < take) {
                uint4 hv = __ldg(reinterpret_cast<const uint4*>(
                               g_xh + (size_t)sidx * D) + ql);
                __half2* hp = reinterpret_cast<__half2*>(&hv);
#pragma unroll
                for (int c = 0; c < 4; c++) {
                    float2 f = __half22float2(hp[c]);
                    a[2 * c]     += f.x;
                    a[2 * c + 1] += f.y;
                }
            }
        }
    }

#pragma unroll
    for (int k = 0; k < 8; k++) a[k] += __shfl_xor_sync(0xffffffffu, a[k], 16);

    float inv = (cnt > 0) ? (1.0f / (float)cnt) : 0.0f;

    if (half == 0) {
        __half2 o[4];
#pragma unroll
        for (int k = 0; k < 4; k++)
            o[k] = __floats2half2_rn(a[2 * k] * inv, a[2 * k + 1] * inv);
        reinterpret_cast<uint4*>(g_S1h + (size_t)gw * D)[ql] =
            *reinterpret_cast<uint4*>(o);
        if (ql == 0) g_mask[gw] = (cnt > 0) ? 1.0f : 0.0f;
    }
}

// ---------------------------------------------------------------------------
// 5) fused GEMM (fp16 HMMA, fp32 accum) + epilogue + state reset
// ---------------------------------------------------------------------------
#define BM  128
#define SAH 168

__device__ __forceinline__ void mma_f16(float* c, const unsigned* a, const unsigned* b)
{
    asm volatile(
        "mma.sync.aligned.m16n8k16.row.col.f32.f16.f16.f32 "
        "{%0,%1,%2,%3}, {%4,%5,%6,%7}, {%8,%9}, {%0,%1,%2,%3};"
        : "+f"(c[0]), "+f"(c[1]), "+f"(c[2]), "+f"(c[3])
        : "r"(a[0]), "r"(a[1]), "r"(a[2]), "r"(a[3]),
          "r"(b[0]), "r"(b[1]));
}

__global__ void __launch_bounds__(256, 2)
gemm_epi_kernel(const float* __restrict__ x,
                const float* __restrict__ b0, const float* __restrict__ b1,
                const float* __restrict__ b2, const float* __restrict__ b3,
                const float* __restrict__ b4,
                float* __restrict__ out, int n)
{
    extern __shared__ __half sm[];
    __half* As = sm;                    // [BM][SAH]
    __half* Bs = sm + (size_t)BM * SAH; // [D][SAH]

    __shared__ float msk[NET][BM];
    __shared__ float bsm[NET][D];

    const float* bp[NET] = {b0, b1, b2, b3, b4};

    int tid  = threadIdx.x;
    int lane = tid & 31;
    int warp = tid >> 5;
    int wm   = (warp & 1) * 64;
    int wn   = (warp >> 1) * 32;
    int lrow = lane >> 2;
    int lcol = lane & 3;
    int row0 = blockIdx.x * BM;

#pragma unroll
    for (int et = 0; et < NET; et++) {
        if (tid < BM) {
            int row = row0 + tid;
            msk[et][tid] = (row < n) ? g_mask[(size_t)et * n + row] : 0.f;
        }
        if (tid < D) bsm[et][tid] = bp[et][tid];
    }

    float c[4][4][4];
#pragma unroll
    for (int s = 0; s < 4; s++)
#pragma unroll
        for (int t = 0; t < 4; t++)
#pragma unroll
            for (int r = 0; r < 4; r++) c[s][t][r] = 0.f;

    __syncthreads();

#pragma unroll 1
    for (int et = 0; et < NET; et++) {
        const __half* __restrict__ S1e = g_S1h + (size_t)et * n * D;
        const __half* __restrict__ S2e = g_S2h + (size_t)et * n * DE;
        const __half* __restrict__ Whe = g_Wh  + (size_t)et * D * KW;

#pragma unroll
        for (int t = 0; t < 10; t++) {
            int idx = tid + t * 256;
            int row = idx / 20;
            int cc  = idx % 20;
            int grow = row0 + row;
            uint4 v = make_uint4(0u, 0u, 0u, 0u);
            if (grow < n) {
                v = (cc < 16)
                  ? __ldg(reinterpret_cast<const uint4*>(S1e + (size_t)grow * D)  + cc)
                  : __ldg(reinterpret_cast<const uint4*>(S2e + (size_t)grow * DE) + (cc - 16));
            }
            *reinterpret_cast<uint4*>(As + (size_t)row * SAH + cc * 8) = v;
        }
#pragma unroll
        for (int t = 0; t < 10; t++) {
            int idx = tid + t * 256;
            int row = idx / 20;
            int cc  = idx % 20;
            uint4 v = __ldg(reinterpret_cast<const uint4*>(Whe + (size_t)row * KW) + cc);
            *reinterpret_cast<uint4*>(Bs + (size_t)row * SAH + cc * 8) = v;
        }
        __syncthreads();

#pragma unroll
        for (int kk = 0; kk < 10; kk++) {
            int k0 = kk * 16;
            unsigned a[4][4], b[4][2];
#pragma unroll
            for (int s = 0; s < 4; s++) {
                int m = wm + s * 16 + lrow;
                const __half* p0 = As + (size_t)m * SAH + k0 + 2 * lcol;
                a[s][0] = *reinterpret_cast<const unsigned*>(p0);
                a[s][1] = *reinterpret_cast<const unsigned*>(p0 + 8 * SAH);
                a[s][2] = *reinterpret_cast<const unsigned*>(p0 + 8);
                a[s][3] = *reinterpret_cast<const unsigned*>(p0 + 8 * SAH + 8);
            }
#pragma unroll
            for (int t = 0; t < 4; t++) {
                int nn = wn + t * 8 + lrow;
                const __half* p0 = Bs + (size_t)nn * SAH + k0 + 2 * lcol;
                b[t][0] = *reinterpret_cast<const unsigned*>(p0);
                b[t][1] = *reinterpret_cast<const unsigned*>(p0 + 8);
            }
#pragma unroll
            for (int s = 0; s < 4; s++)
#pragma unroll
                for (int t = 0; t < 4; t++)
                    mma_f16(c[s][t], a[s], b[t]);
        }
        __syncthreads();
    }

    // epilogue
#pragma unroll
    for (int s = 0; s < 4; s++) {
#pragma unroll
        for (int h = 0; h < 2; h++) {
            int mloc = wm + s * 16 + lrow + h * 8;
            int grow = row0 + mloc;
            if (grow >= n) continue;
            float mk[NET];
#pragma unroll
            for (int et = 0; et < NET; et++) mk[et] = msk[et][mloc];
#pragma unroll
            for (int t = 0; t < 4; t++) {
                int ncol = wn + t * 8 + lcol * 2;
                float bs0 = 0.f, bs1 = 0.f;
#pragma unroll
                for (int et = 0; et < NET; et++) {
                    if (mk[et] > 0.f) {
                        bs0 += bsm[et][ncol];
                        bs1 += bsm[et][ncol + 1];
                    }
                }
                float c0 = c[s][t][h * 2 + 0];
                float c1 = c[s][t][h * 2 + 1];
                const float* xp = x + (size_t)grow * D + ncol;
                float2 o;
                o.x = fmaxf(xp[0] + (c0 + bs0) * 0.2f, 0.f);
                o.y = fmaxf(xp[1] + (c1 + bs1) * 0.2f, 0.f);
                *reinterpret_cast<float2*>(out + (size_t)grow * D + ncol) = o;
            }
        }
    }

    // state reset for next replay: zero degrees + allocator
    int zi = blockIdx.x * blockDim.x + threadIdx.x;
    int zs = gridDim.x * blockDim.x;
    for (int z = zi; z < NET * n; z += zs) g_deg[z] = 0;
    if (zi == 0) g_total = 0;
}

// ---------------------------------------------------------------------------
extern "C" void kernel_launch(void* const* d_in, const int* in_sizes, int n_in,
                              void* d_out, int out_size)
{
    const float* x = (const float*)d_in[0];
    int n = in_sizes[0] / D;
    if (n > MAXN) return;

    EdgeMeta em;
    WPtrs wp;
    const float* b[NET];
    int maxE = 0, totE = 0;
    for (int et = 0; et < NET; et++) {
        em.ef[et]  = (const float*)d_in[1 + 5 * et + 0];
        wp.W[et]   = (const float*)d_in[1 + 5 * et + 1];
        b[et]      = (const float*)d_in[1 + 5 * et + 2];
        em.src[et] = (const int*)  d_in[1 + 5 * et + 3];
        em.dst[et] = (const int*)  d_in[1 + 5 * et + 4];
        em.E[et]   = in_sizes[1 + 5 * et + 3];
        if (em.E[et] > maxE) maxE = em.E[et];
        totE += em.E[et];
    }
    if (totE > CAP_TOTAL) return;
    float* out = (float*)d_out;

    int nelem = NET * n;

    static int smem_bytes = 2 * BM * SAH * (int)sizeof(__half);
    cudaFuncSetAttribute(gemm_epi_kernel,
                         cudaFuncAttributeMaxDynamicSharedMemorySize, smem_bytes);

    // 1) fused prep + count
    {
        int nx = n * D / 8;
        int nw = NET * D * KW;
        int work = nx + nw + totE;
        count_prep_kernel<<<(work + 255) / 256, 256>>>(x, wp, em, n, nx, nw);
    }
    // 2) alloc
    alloc_kernel<<<(nelem + 255) / 256, 256>>>(nelem);
    // 3) fill
    {
        dim3 grid((maxE + 255) / 256, NET);
        fill_kernel<<<grid, 256>>>(em, n);
    }
    // 4) ef means (feature-per-lane; profiled launch)
    {
        int blocks = (nelem * 32 + 255) / 256;
        efmean_kernel<<<blocks, 256>>>(em, n);
    }
    // 5) gather x-only
    {
        int blocks = (nelem * 32 + 255) / 256;
        gather_kernel<<<blocks, 256>>>(n);
    }
    // 6) fused GEMM + epilogue + reset
    {
        int blocks = (n + BM - 1) / BM;
        gemm_epi_kernel<<<blocks, 256, smem_bytes>>>(
            x, b[0], b[1], b[2], b[3], b[4], out, n);
    }
}